// round 2
// baseline (speedup 1.0000x reference)
#include <cuda_runtime.h>
#include <cuda_bf16.h>

// TripletLoss: batch-all triplet loss with per-anchor class-size weights.
// x:[384,256] f32, labels:[384] i32 -> scalar f32.
//
// num = sum_a count_a * sum_{p>a, lab[p]==lab[a]} sum_{n: lab[n]!=lab[a]}
//                       relu(MARGIN + d2[a,p] - d2[a,n])
// den = sum of the same weights over valid triplets
// out = den > 0 ? num/den : 0

#define BN 384
#define DD 256
#define TPB 384
#define NW (TPB / 32)
#define MARGIN_F 0.2f

__device__ float g_num[BN];
__device__ float g_den[BN];

__global__ void __launch_bounds__(TPB) triplet_main_kernel(
    const float* __restrict__ x, const int* __restrict__ labels)
{
    __shared__ float xa[DD];     // anchor row
    __shared__ float d2[BN];     // dist2[a, :]
    __shared__ int   lab[BN];
    __shared__ int   plist[BN];  // valid positives (p > a, same label)
    __shared__ int   np_s;
    __shared__ float red_s[NW];
    __shared__ float red_c[NW];
    __shared__ int   red_k[NW];

    const int a = blockIdx.x;
    const int t = threadIdx.x;
    const int w = t >> 5;
    const int L = t & 31;

    if (t < DD) xa[t] = x[a * DD + t];
    lab[t] = labels[t];
    if (t == 0) np_s = 0;
    __syncthreads();

    const int la = lab[a];

    // Anchor slice in registers: lane L owns dims L, L+32, ..., L+224
    float xr[8];
#pragma unroll
    for (int k = 0; k < 8; ++k) xr[k] = xa[L + 32 * k];

    // Cooperative dist2 row: warp w computes j in [w*32, w*32+32).
    // Lanes split the D dimension (coalesced), then butterfly-reduce.
    for (int jj = 0; jj < 32; ++jj) {
        const int j = w * 32 + jj;
        const float* __restrict__ xj = x + j * DD;
        float s = 0.0f;
#pragma unroll
        for (int k = 0; k < 8; ++k) {
            float diff = xr[k] - xj[L + 32 * k];
            s = fmaf(diff, diff, s);
        }
#pragma unroll
        for (int o = 16; o > 0; o >>= 1)
            s += __shfl_xor_sync(0xffffffffu, s, o);
        if (L == 0) d2[j] = s;
    }

    // Compact valid positives: p > a with same label.
    if (t > a && lab[t] == la) {
        int pos = atomicAdd(&np_s, 1);
        plist[pos] = t;
    }
    __syncthreads();

    const int np = np_s;

    // Each thread owns negative n = t; loop over the (tiny) positive list.
    float s = 0.0f;
    int cnt = 0;
    {
        const bool is_neg = (lab[t] != la);
        if (is_neg) {
            const float dn = d2[t];
            for (int pi = 0; pi < np; ++pi) {
                const float dap = d2[plist[pi]];
                s += fmaxf(MARGIN_F + dap - dn, 0.0f);
            }
            cnt = np;
        }
    }

    // count_a = #samples sharing anchor's label (duplication weight)
    int ka = (lab[t] == la) ? 1 : 0;

    // Block reduction of s, cnt, ka
#pragma unroll
    for (int o = 16; o > 0; o >>= 1) {
        s   += __shfl_xor_sync(0xffffffffu, s, o);
        cnt += __shfl_xor_sync(0xffffffffu, cnt, o);
        ka  += __shfl_xor_sync(0xffffffffu, ka, o);
    }
    if (L == 0) { red_s[w] = s; red_c[w] = (float)cnt; red_k[w] = ka; }
    __syncthreads();

    if (t == 0) {
        float S = 0.0f, C = 0.0f;
        int K = 0;
#pragma unroll
        for (int i = 0; i < NW; ++i) { S += red_s[i]; C += red_c[i]; K += red_k[i]; }
        const float kf = (float)K;
        g_num[a] = kf * S;
        g_den[a] = kf * C;
    }
}

__global__ void __launch_bounds__(TPB) triplet_reduce_kernel(float* __restrict__ out)
{
    __shared__ float rs[NW];
    __shared__ float rc[NW];
    const int t = threadIdx.x;
    const int w = t >> 5;
    const int L = t & 31;

    float s = g_num[t];
    float c = g_den[t];
#pragma unroll
    for (int o = 16; o > 0; o >>= 1) {
        s += __shfl_xor_sync(0xffffffffu, s, o);
        c += __shfl_xor_sync(0xffffffffu, c, o);
    }
    if (L == 0) { rs[w] = s; rc[w] = c; }
    __syncthreads();

    if (t == 0) {
        float S = 0.0f, C = 0.0f;
#pragma unroll
        for (int i = 0; i < NW; ++i) { S += rs[i]; C += rc[i]; }
        out[0] = (C > 0.0f) ? (S / C) : 0.0f;
    }
}

extern "C" void kernel_launch(void* const* d_in, const int* in_sizes, int n_in,
                              void* d_out, int out_size)
{
    const float* x      = (const float*)d_in[0];
    const int*   labels = (const int*)d_in[1];
    float*       out    = (float*)d_out;

    triplet_main_kernel<<<BN, TPB>>>(x, labels);
    triplet_reduce_kernel<<<1, TPB>>>(out);
}

// round 3
// speedup vs baseline: 1.1065x; 1.1065x over previous
#include <cuda_runtime.h>
#include <cuda_bf16.h>

// Fused batch-all triplet loss. x:[384,256] f32, labels:[384] i32 -> scalar f32.
// 96 blocks x 384 threads; each block computes d2 rows for 4 anchors with one
// pass over x (L2 traffic = 96 * 393KB), then the triplet sums, then the last
// block to finish does the deterministic global reduction.

#define BN 384
#define DD 256
#define TPB 384
#define NB 96          // blocks; 4 anchors each
#define ANC 4
#define NW (TPB / 32)
#define MARGIN_F 0.2f

typedef unsigned long long ull;

__device__ float g_num[NB];
__device__ float g_den[NB];
__device__ int   g_count = 0;

static __device__ __forceinline__ ull pk2(float lo, float hi) {
    ull r; asm("mov.b64 %0, {%1, %2};" : "=l"(r) : "f"(lo), "f"(hi)); return r;
}
static __device__ __forceinline__ void upk2(ull v, float& lo, float& hi) {
    asm("mov.b64 {%0, %1}, %2;" : "=f"(lo), "=f"(hi) : "l"(v));
}
static __device__ __forceinline__ ull fma2(ull a, ull b, ull c) {
    ull d; asm("fma.rn.f32x2 %0, %1, %2, %3;" : "=l"(d) : "l"(a), "l"(b), "l"(c)); return d;
}

__global__ void __launch_bounds__(TPB, 1) triplet_fused_kernel(
    const float* __restrict__ x, const int* __restrict__ labels,
    float* __restrict__ out)
{
    __shared__ int           lab[BN];
    __shared__ float         d2s[ANC][BN];
    __shared__ unsigned int  pmask[ANC][NW];   // p > a, same label
    __shared__ unsigned int  cmask[ANC][NW];   // same label (class size)
    __shared__ int           plist[ANC][48];
    __shared__ int           np_s[ANC];
    __shared__ int           kc_s[ANC];
    __shared__ float         redn[NW], redd[NW];
    __shared__ int           lastflag;
    __shared__ float         rn[NB], rd[NB];

    const int t    = threadIdx.x;
    const int w    = t >> 5;
    const int L    = t & 31;
    const int s    = L & 15;       // lane within 16-lane j-group
    const int half = L >> 4;       // which j of the pair
    const int a0   = blockIdx.x * ANC;

    lab[t] = labels[t];
    __syncthreads();

    // ---- deterministic positive lists + class counts via ballots ----
    const int myl = lab[t];
#pragma unroll
    for (int i = 0; i < ANC; ++i) {
        const int lai = lab[a0 + i];
        unsigned m_same = __ballot_sync(0xffffffffu, myl == lai);
        unsigned m_pos  = __ballot_sync(0xffffffffu, (myl == lai) && (t > a0 + i));
        if (L == 0) { cmask[i][w] = m_same; pmask[i][w] = m_pos; }
    }
    // (no sync needed before the independent dist loop; plist built below by t<4
    //  and consumed only after the next __syncthreads)
    __syncthreads();
    if (t < ANC) {
        int c = 0, k = 0;
#pragma unroll
        for (int w2 = 0; w2 < NW; ++w2) {
            k += __popc(cmask[t][w2]);
            unsigned mm = pmask[t][w2];
            while (mm) {
                int b = __ffs(mm) - 1;
                mm &= mm - 1;
                plist[t][c++] = w2 * 32 + b;   // ascending -> deterministic order
            }
        }
        np_s[t] = c;
        kc_s[t] = k;
    }

    // ---- anchor fragments (lane owns dims {4*(16q+s)..+4}, q=0..3) ----
    ull af[ANC][8];
    float na[ANC];
#pragma unroll
    for (int i = 0; i < ANC; ++i) {
        const float4* xa4 = (const float4*)(x + (a0 + i) * DD);
#pragma unroll
        for (int q = 0; q < 4; ++q) {
            float4 v = __ldg(&xa4[(q << 4) + s]);
            af[i][2 * q]     = pk2(v.x, v.y);
            af[i][2 * q + 1] = pk2(v.z, v.w);
        }
        ull an = 0ull;
#pragma unroll
        for (int u = 0; u < 8; ++u) an = fma2(af[i][u], af[i][u], an);
        float lo, hi; upk2(an, lo, hi);
        float nap = lo + hi;
#pragma unroll
        for (int o = 8; o > 0; o >>= 1) nap += __shfl_xor_sync(0xffffffffu, nap, o);
        na[i] = nap;
    }

    // ---- main loop: warp w computes d2[a0..a0+3][32w..32w+32) ----
    // 16 batches of 2 j's; 16-lane groups split D; dot-product formulation.
    for (int b = 0; b < 16; ++b) {
        const int j = (w << 5) + (b << 1) + half;
        const float4* xj4 = (const float4*)(x + j * DD);

        float4 q0 = __ldg(&xj4[s]);
        float4 q1 = __ldg(&xj4[16 + s]);
        float4 q2 = __ldg(&xj4[32 + s]);
        float4 q3 = __ldg(&xj4[48 + s]);

        ull xp[8];
        xp[0] = pk2(q0.x, q0.y); xp[1] = pk2(q0.z, q0.w);
        xp[2] = pk2(q1.x, q1.y); xp[3] = pk2(q1.z, q1.w);
        xp[4] = pk2(q2.x, q2.y); xp[5] = pk2(q2.z, q2.w);
        xp[6] = pk2(q3.x, q3.y); xp[7] = pk2(q3.z, q3.w);

        ull accn = 0ull, ac0 = 0ull, ac1 = 0ull, ac2 = 0ull, ac3 = 0ull;
#pragma unroll
        for (int u = 0; u < 8; ++u) {
            accn = fma2(xp[u], xp[u], accn);
            ac0  = fma2(af[0][u], xp[u], ac0);
            ac1  = fma2(af[1][u], xp[u], ac1);
            ac2  = fma2(af[2][u], xp[u], ac2);
            ac3  = fma2(af[3][u], xp[u], ac3);
        }
        float v[5];
        {
            float lo, hi;
            upk2(accn, lo, hi); v[0] = lo + hi;
            upk2(ac0,  lo, hi); v[1] = lo + hi;
            upk2(ac1,  lo, hi); v[2] = lo + hi;
            upk2(ac2,  lo, hi); v[3] = lo + hi;
            upk2(ac3,  lo, hi); v[4] = lo + hi;
        }
#pragma unroll
        for (int o = 8; o > 0; o >>= 1) {
#pragma unroll
            for (int k = 0; k < 5; ++k)
                v[k] += __shfl_xor_sync(0xffffffffu, v[k], o);
        }
        if (s == 0) {
#pragma unroll
            for (int i = 0; i < ANC; ++i)
                d2s[i][j] = na[i] + v[0] - 2.0f * v[i + 1];
        }
    }
    __syncthreads();

    // ---- triplet phase: thread t -> anchor i = t/96, negatives sub+96r ----
    const int i   = t / 96;
    const int sub = t - i * 96;
    const int lai = lab[a0 + i];
    const int npi = np_s[i];
    const float* row = d2s[i];

    float sp = 0.0f;
    int   cp = 0;
#pragma unroll
    for (int r = 0; r < 4; ++r) {
        const int n = sub + 96 * r;
        if (lab[n] != lai) {
            const float dn = row[n];
            for (int p = 0; p < npi; ++p)
                sp += fmaxf(MARGIN_F + row[plist[i][p]] - dn, 0.0f);
            cp += npi;
        }
    }
    const float kf = (float)kc_s[i];
    float sw = kf * sp;
    float cw = kf * (float)cp;

#pragma unroll
    for (int o = 16; o > 0; o >>= 1) {
        sw += __shfl_xor_sync(0xffffffffu, sw, o);
        cw += __shfl_xor_sync(0xffffffffu, cw, o);
    }
    if (L == 0) { redn[w] = sw; redd[w] = cw; }
    __syncthreads();

    if (t == 0) {
        float S = 0.0f, C = 0.0f;
#pragma unroll
        for (int u = 0; u < NW; ++u) { S += redn[u]; C += redd[u]; }
        g_num[blockIdx.x] = S;
        g_den[blockIdx.x] = C;
        __threadfence();
        int old = atomicAdd(&g_count, 1);
        lastflag = (old == NB - 1);
    }
    __syncthreads();

    if (lastflag) {
        __threadfence();
        if (t < NB) { rn[t] = g_num[t]; rd[t] = g_den[t]; }
        __syncthreads();
        if (t == 0) {
            float S = 0.0f, C = 0.0f;
#pragma unroll
            for (int u = 0; u < NB; ++u) { S += rn[u]; C += rd[u]; }
            out[0] = (C > 0.0f) ? (S / C) : 0.0f;
            g_count = 0;   // reset for next graph replay
        }
    }
}

extern "C" void kernel_launch(void* const* d_in, const int* in_sizes, int n_in,
                              void* d_out, int out_size)
{
    const float* x      = (const float*)d_in[0];
    const int*   labels = (const int*)d_in[1];
    float*       out    = (float*)d_out;

    triplet_fused_kernel<<<NB, TPB>>>(x, labels, out);
}